// round 10
// baseline (speedup 1.0000x reference)
#include <cuda_runtime.h>
#include <cstdint>

// ---------------------------------------------------------------------------
// Problem constants
// ---------------------------------------------------------------------------
#define Bb 4
#define Nn 2048
#define Cc 1024
#define Hh 16
#define Dd 64
#define M_TOT (Bb * Nn)        // 8192
#define QKV_N (3 * Cc)         // 3072

__device__ float g_qkv[(size_t)M_TOT * QKV_N];   // [B*N, 3C]
__device__ float g_y[(size_t)M_TOT * Cc];        // [B*N, C]

// ---------------------------------------------------------------------------
// Tiled fp32 GEMM: C[M,N] = A[M,K] @ B[K,N], row-major.
// 128x128 tile, BK=16, 256 threads, 8x8 register microtile (two 4-row/4-col
// chunks at stride 64), float4 shared loads. FMA-pipe-bound by design.
// ---------------------------------------------------------------------------
#define BM 128
#define BN 128
#define BK 16
#define APAD 4
#define BPAD 4

__device__ __forceinline__ void gemm128(const float* __restrict__ A,
                                        const float* __restrict__ B,
                                        float* __restrict__ C,
                                        int M, int N, int K) {
    __shared__ float As[BK][BM + APAD];  // transposed: As[k][m]
    __shared__ float Bs[BK][BN + BPAD];

    const int tid = threadIdx.x;
    const int tx = tid & 15;
    const int ty = tid >> 4;
    const int row0 = blockIdx.y * BM;
    const int col0 = blockIdx.x * BN;

    float acc[8][8] = {};

    for (int k0 = 0; k0 < K; k0 += BK) {
        // A tile: 128 rows x 16 cols = 512 float4 loads, stored transposed
        #pragma unroll
        for (int i = tid; i < (BM * BK) / 4; i += 256) {
            int r  = i >> 2;
            int c4 = (i & 3) << 2;
            float4 v = *(const float4*)&A[(size_t)(row0 + r) * K + k0 + c4];
            As[c4 + 0][r] = v.x;
            As[c4 + 1][r] = v.y;
            As[c4 + 2][r] = v.z;
            As[c4 + 3][r] = v.w;
        }
        // B tile: 16 rows x 128 cols = 512 float4 loads, direct
        #pragma unroll
        for (int i = tid; i < (BK * BN) / 4; i += 256) {
            int r  = i >> 5;
            int c4 = (i & 31) << 2;
            *(float4*)&Bs[r][c4] = *(const float4*)&B[(size_t)(k0 + r) * N + col0 + c4];
        }
        __syncthreads();

        #pragma unroll
        for (int kk = 0; kk < BK; kk++) {
            float4 a0 = *(const float4*)&As[kk][ty * 4];
            float4 a1 = *(const float4*)&As[kk][ty * 4 + 64];
            float4 b0 = *(const float4*)&Bs[kk][tx * 4];
            float4 b1 = *(const float4*)&Bs[kk][tx * 4 + 64];
            float av[8] = {a0.x, a0.y, a0.z, a0.w, a1.x, a1.y, a1.z, a1.w};
            float bv[8] = {b0.x, b0.y, b0.z, b0.w, b1.x, b1.y, b1.z, b1.w};
            #pragma unroll
            for (int i = 0; i < 8; i++)
                #pragma unroll
                for (int j = 0; j < 8; j++)
                    acc[i][j] = fmaf(av[i], bv[j], acc[i][j]);
        }
        __syncthreads();
    }

    // Epilogue: 16 float4 stores
    #pragma unroll
    for (int i = 0; i < 8; i++) {
        int r = row0 + ty * 4 + ((i < 4) ? i : (64 + i - 4));
        float4 v0 = make_float4(acc[i][0], acc[i][1], acc[i][2], acc[i][3]);
        float4 v1 = make_float4(acc[i][4], acc[i][5], acc[i][6], acc[i][7]);
        *(float4*)&C[(size_t)r * N + col0 + tx * 4]      = v0;
        *(float4*)&C[(size_t)r * N + col0 + tx * 4 + 64] = v1;
    }
}

__global__ __launch_bounds__(256, 2) void qkv_gemm_kernel(const float* __restrict__ x,
                                                          const float* __restrict__ w_attn) {
    gemm128(x, w_attn, g_qkv, M_TOT, QKV_N, Cc);
}

__global__ __launch_bounds__(256, 2) void proj_gemm_kernel(const float* __restrict__ w_proj,
                                                           float* __restrict__ out) {
    gemm128(g_y, w_proj, out, M_TOT, Cc, Cc);
}

// Diagnostic sentinel: fills out with a large constant so a binding failure is
// distinguishable (rel_err ~3e4) from an unwritten output (rel_err = 1.0).
__global__ void sentinel_fill_kernel(float* out, int n) {
    int i = blockIdx.x * blockDim.x + threadIdx.x;
    if (i < n) out[i] = 1.0e6f;
}

// ---------------------------------------------------------------------------
// Flash attention (non-causal), fp32 SIMT, online softmax.
// grid.y = b*H + h, grid.x = q-tile (64 rows). 256 threads.
// Each thread: 4 q-rows (ty + 16i) x 4 cols (tx + 16j) register tile.
// Smem rows padded to 65 floats -> conflict-free scalar LDS both phases.
// ---------------------------------------------------------------------------
#define TPAD 65
#define TSZ  (64 * TPAD)

__global__ __launch_bounds__(256) void attn_kernel() {
    extern __shared__ float fsmem[];
    float* Qs = fsmem;
    float* Ks = fsmem + TSZ;
    float* Vs = fsmem + 2 * TSZ;
    float* Ps = fsmem + 3 * TSZ;

    const int bh = blockIdx.y;
    const int b  = bh / Hh;
    const int h  = bh % Hh;
    const int q0 = blockIdx.x * 64;
    const int tx = threadIdx.x & 15;
    const int ty = threadIdx.x >> 4;

    const float* qbase = g_qkv + (size_t)b * Nn * QKV_N + (size_t)h * Dd;
    const float* kbase = qbase + Cc;
    const float* vbase = qbase + 2 * Cc;

    // Load Q tile [64][Dd] via float4
    #pragma unroll
    for (int i = threadIdx.x; i < 64 * (Dd / 4); i += 256) {
        int r  = i >> 4;
        int c4 = (i & 15) << 2;
        float4 v = *(const float4*)&qbase[(size_t)(q0 + r) * QKV_N + c4];
        float* q = &Qs[r * TPAD + c4];
        q[0] = v.x; q[1] = v.y; q[2] = v.z; q[3] = v.w;
    }

    float o[4][4] = {};
    float m[4], l[4];
    #pragma unroll
    for (int i = 0; i < 4; i++) { m[i] = -1e30f; l[i] = 0.0f; }

    const float scale = 0.125f;   // 1/sqrt(64)

    for (int k0 = 0; k0 < Nn; k0 += 64) {
        __syncthreads();   // previous iter's Ks/Vs/Ps reads done
        #pragma unroll
        for (int i = threadIdx.x; i < 64 * (Dd / 4); i += 256) {
            int r  = i >> 4;
            int c4 = (i & 15) << 2;
            float4 kv = *(const float4*)&kbase[(size_t)(k0 + r) * QKV_N + c4];
            float4 vv = *(const float4*)&vbase[(size_t)(k0 + r) * QKV_N + c4];
            float* kd = &Ks[r * TPAD + c4];
            float* vd = &Vs[r * TPAD + c4];
            kd[0] = kv.x; kd[1] = kv.y; kd[2] = kv.z; kd[3] = kv.w;
            vd[0] = vv.x; vd[1] = vv.y; vd[2] = vv.z; vd[3] = vv.w;
        }
        __syncthreads();   // also covers Qs on first iteration

        // S = scale * Q K^T
        float s[4][4] = {};
        #pragma unroll 8
        for (int d = 0; d < Dd; d++) {
            float a[4], kv[4];
            #pragma unroll
            for (int i = 0; i < 4; i++) a[i]  = Qs[(ty + 16 * i) * TPAD + d];
            #pragma unroll
            for (int j = 0; j < 4; j++) kv[j] = Ks[(tx + 16 * j) * TPAD + d];
            #pragma unroll
            for (int i = 0; i < 4; i++)
                #pragma unroll
                for (int j = 0; j < 4; j++)
                    s[i][j] = fmaf(a[i], kv[j], s[i][j]);
        }

        // Online softmax update per owned row (16 threads with same ty share a row)
        #pragma unroll
        for (int i = 0; i < 4; i++) {
            float tmax = -1e30f;
            #pragma unroll
            for (int j = 0; j < 4; j++) {
                s[i][j] *= scale;
                tmax = fmaxf(tmax, s[i][j]);
            }
            #pragma unroll
            for (int msk = 1; msk < 16; msk <<= 1)
                tmax = fmaxf(tmax, __shfl_xor_sync(0xffffffffu, tmax, msk));

            float newm = fmaxf(m[i], tmax);
            float psum = 0.0f;
            #pragma unroll
            for (int j = 0; j < 4; j++) {
                s[i][j] = __expf(s[i][j] - newm);
                psum += s[i][j];
            }
            #pragma unroll
            for (int msk = 1; msk < 16; msk <<= 1)
                psum += __shfl_xor_sync(0xffffffffu, psum, msk);

            float corr = __expf(m[i] - newm);
            l[i] = l[i] * corr + psum;
            m[i] = newm;
            #pragma unroll
            for (int k = 0; k < 4; k++) o[i][k] *= corr;
        }

        // Stage P tile to smem for the PV product
        #pragma unroll
        for (int i = 0; i < 4; i++)
            #pragma unroll
            for (int j = 0; j < 4; j++)
                Ps[(ty + 16 * i) * TPAD + tx + 16 * j] = s[i][j];
        __syncthreads();

        // O += P @ V
        #pragma unroll 8
        for (int j = 0; j < 64; j++) {
            float p[4], v[4];
            #pragma unroll
            for (int i = 0; i < 4; i++) p[i] = Ps[(ty + 16 * i) * TPAD + j];
            #pragma unroll
            for (int k = 0; k < 4; k++) v[k] = Vs[j * TPAD + tx + 16 * k];
            #pragma unroll
            for (int i = 0; i < 4; i++)
                #pragma unroll
                for (int k = 0; k < 4; k++)
                    o[i][k] = fmaf(p[i], v[k], o[i][k]);
        }
    }

    // Normalize and write y[b, q0+r, h*64 + d]
    #pragma unroll
    for (int i = 0; i < 4; i++) {
        float inv_l = 1.0f / l[i];
        int n = q0 + ty + 16 * i;
        float* yrow = g_y + (size_t)(b * Nn + n) * Cc + h * Dd;
        #pragma unroll
        for (int k = 0; k < 4; k++)
            yrow[tx + 16 * k] = o[i][k] * inv_l;
    }
}

// ---------------------------------------------------------------------------
// Launch. Binding accepts in_sizes as ELEMENT counts or BYTE counts; tries
// positional order first, then size-keyed. If unresolved, writes a sentinel
// (1e6) so the failure is distinguishable in rel_err.
// ---------------------------------------------------------------------------
static inline bool size_is(int got, long long elems) {
    return got == (int)elems || got == (int)(elems * 4);
}

extern "C" void kernel_launch(void* const* d_in, const int* in_sizes, int n_in,
                              void* d_out, int out_size) {
    const float* x      = nullptr;
    const float* w_attn = nullptr;
    const float* w_proj = nullptr;

    // Positional first (metadata order: x, w_attn, w_proj)
    if (n_in >= 3 &&
        size_is(in_sizes[0], (long long)M_TOT * Cc) &&
        size_is(in_sizes[1], (long long)Cc * QKV_N) &&
        size_is(in_sizes[2], (long long)Cc * Cc)) {
        x      = (const float*)d_in[0];
        w_attn = (const float*)d_in[1];
        w_proj = (const float*)d_in[2];
    } else {
        // Size-keyed (element- or byte-count match)
        for (int i = 0; i < n_in; i++) {
            if      (size_is(in_sizes[i], (long long)M_TOT * Cc)) x      = (const float*)d_in[i];
            else if (size_is(in_sizes[i], (long long)Cc * QKV_N)) w_attn = (const float*)d_in[i];
            else if (size_is(in_sizes[i], (long long)Cc * Cc))    w_proj = (const float*)d_in[i];
        }
    }
    float* out = (float*)d_out;

    if (!x || !w_attn || !w_proj) {
        // Binding failed: deterministic sentinel fill -> rel_err ~3e4 signature.
        int n = M_TOT * Cc;   // expected out elements
        if (out_size >= n || out_size == n * 4 || out_size == n) { /* keep n */ }
        sentinel_fill_kernel<<<(n + 255) / 256, 256>>>(out, n);
        return;
    }

    // 1) QKV projection: [8192,1024] @ [1024,3072]
    qkv_gemm_kernel<<<dim3(QKV_N / BN, M_TOT / BM), 256>>>(x, w_attn);

    // 2) Flash attention (fp32 SIMT)
    {
        const int attn_smem = 4 * TSZ * (int)sizeof(float);   // 66,560 B
        cudaFuncSetAttribute(attn_kernel, cudaFuncAttributeMaxDynamicSharedMemorySize, attn_smem);
        attn_kernel<<<dim3(Nn / 64, Bb * Hh), 256, attn_smem>>>();
    }

    // 3) Output projection: [8192,1024] @ [1024,1024]
    proj_gemm_kernel<<<dim3(Cc / BN, M_TOT / BM), 256>>>(w_proj, out);
}

// round 17
// speedup vs baseline: 1.0630x; 1.0630x over previous
#include <cuda_runtime.h>
#include <cstdint>

// ---------------------------------------------------------------------------
// Problem constants
// ---------------------------------------------------------------------------
#define Bb 4
#define Nn 2048
#define Cc 1024
#define Hh 16
#define Dd 64
#define M_TOT (Bb * Nn)        // 8192
#define QKV_N (3 * Cc)         // 3072

__device__ float g_qkv[(size_t)M_TOT * QKV_N];   // [B*N, 3C]
__device__ float g_y[(size_t)M_TOT * Cc];        // [B*N, C]

// ---------------------------------------------------------------------------
// Packed fp32x2 helpers (Blackwell sm_100+ base ISA; per-lane IEEE .rn —
// results are bit-identical to two scalar fmaf's).
// ---------------------------------------------------------------------------
typedef unsigned long long u64;

__device__ __forceinline__ u64 pk2(float lo, float hi) {
    u64 r;
    asm("mov.b64 %0, {%1, %2};"
        : "=l"(r) : "r"(__float_as_uint(lo)), "r"(__float_as_uint(hi)));
    return r;
}
__device__ __forceinline__ void upk2(u64 v, float& lo, float& hi) {
    unsigned int a, b;
    asm("mov.b64 {%0, %1}, %2;" : "=r"(a), "=r"(b) : "l"(v));
    lo = __uint_as_float(a);
    hi = __uint_as_float(b);
}
__device__ __forceinline__ void fma2(u64& d, u64 a, u64 b) {
    asm("fma.rn.f32x2 %0, %1, %2, %0;" : "+l"(d) : "l"(a), "l"(b));
}
__device__ __forceinline__ u64 mul2(u64 a, u64 b) {
    u64 r;
    asm("mul.rn.f32x2 %0, %1, %2;" : "=l"(r) : "l"(a), "l"(b));
    return r;
}

// ---------------------------------------------------------------------------
// Tiled fp32 GEMM (structure identical to the PASSING round-10 kernel):
// C[M,N] = A[M,K] @ B[K,N]. 128x128 tile, BK=16, 256 threads, 8x8 microtile.
// ONLY change: inner product uses packed fma.rn.f32x2 (32 FFMA2 vs 64 FFMA).
// ---------------------------------------------------------------------------
#define BM 128
#define BN 128
#define BK 16
#define APAD 4
#define BPAD 4

__device__ __forceinline__ void gemm128(const float* __restrict__ A,
                                        const float* __restrict__ B,
                                        float* __restrict__ C,
                                        int M, int N, int K) {
    __shared__ float As[BK][BM + APAD];  // transposed: As[k][m]
    __shared__ float Bs[BK][BN + BPAD];

    const int tid = threadIdx.x;
    const int tx = tid & 15;
    const int ty = tid >> 4;
    const int row0 = blockIdx.y * BM;
    const int col0 = blockIdx.x * BN;

    u64 accp[8][4] = {};   // packed pairs: accp[i][jp] = (acc[i][2jp], acc[i][2jp+1])

    for (int k0 = 0; k0 < K; k0 += BK) {
        // A tile: 128 rows x 16 cols, stored transposed
        #pragma unroll
        for (int i = tid; i < (BM * BK) / 4; i += 256) {
            int r  = i >> 2;
            int c4 = (i & 3) << 2;
            float4 v = *(const float4*)&A[(size_t)(row0 + r) * K + k0 + c4];
            As[c4 + 0][r] = v.x;
            As[c4 + 1][r] = v.y;
            As[c4 + 2][r] = v.z;
            As[c4 + 3][r] = v.w;
        }
        // B tile: 16 rows x 128 cols, direct
        #pragma unroll
        for (int i = tid; i < (BK * BN) / 4; i += 256) {
            int r  = i >> 5;
            int c4 = (i & 31) << 2;
            *(float4*)&Bs[r][c4] = *(const float4*)&B[(size_t)(k0 + r) * N + col0 + c4];
        }
        __syncthreads();

        #pragma unroll
        for (int kk = 0; kk < BK; kk++) {
            float4 a0 = *(const float4*)&As[kk][ty * 4];
            float4 a1 = *(const float4*)&As[kk][ty * 4 + 64];
            float4 b0 = *(const float4*)&Bs[kk][tx * 4];
            float4 b1 = *(const float4*)&Bs[kk][tx * 4 + 64];
            u64 bp[4] = {pk2(b0.x, b0.y), pk2(b0.z, b0.w),
                         pk2(b1.x, b1.y), pk2(b1.z, b1.w)};
            float av[8] = {a0.x, a0.y, a0.z, a0.w, a1.x, a1.y, a1.z, a1.w};
            #pragma unroll
            for (int i = 0; i < 8; i++) {
                u64 ad = pk2(av[i], av[i]);
                #pragma unroll
                for (int jp = 0; jp < 4; jp++)
                    fma2(accp[i][jp], ad, bp[jp]);
            }
        }
        __syncthreads();
    }

    // Epilogue: unpack pairs -> same float4 stores as baseline
    #pragma unroll
    for (int i = 0; i < 8; i++) {
        int r = row0 + ty * 4 + ((i < 4) ? i : (64 + i - 4));
        float c0, c1, c2, c3, c4v, c5, c6, c7;
        upk2(accp[i][0], c0, c1);
        upk2(accp[i][1], c2, c3);
        upk2(accp[i][2], c4v, c5);
        upk2(accp[i][3], c6, c7);
        *(float4*)&C[(size_t)r * N + col0 + tx * 4]      = make_float4(c0, c1, c2, c3);
        *(float4*)&C[(size_t)r * N + col0 + tx * 4 + 64] = make_float4(c4v, c5, c6, c7);
    }
}

__global__ __launch_bounds__(256, 2) void qkv_gemm_kernel(const float* __restrict__ x,
                                                          const float* __restrict__ w_attn) {
    gemm128(x, w_attn, g_qkv, M_TOT, QKV_N, Cc);
}

__global__ __launch_bounds__(256, 2) void proj_gemm_kernel(const float* __restrict__ w_proj,
                                                           float* __restrict__ out) {
    gemm128(g_y, w_proj, out, M_TOT, Cc, Cc);
}

// Diagnostic sentinel (binding-failure signature distinct from 1.0).
__global__ void sentinel_fill_kernel(float* out, int n) {
    int i = blockIdx.x * blockDim.x + threadIdx.x;
    if (i < n) out[i] = 1.0e6f;
}

// ---------------------------------------------------------------------------
// Flash attention (non-causal), fp32 SIMT — structure identical to the
// PASSING round-10 kernel. ONLY change: QK^T and PV inner loops use packed
// fma.rn.f32x2; softmax stays scalar (unpack/repack at tile boundaries).
// ---------------------------------------------------------------------------
#define TPAD 65
#define TSZ  (64 * TPAD)

__global__ __launch_bounds__(256) void attn_kernel() {
    extern __shared__ float fsmem[];
    float* Qs = fsmem;
    float* Ks = fsmem + TSZ;
    float* Vs = fsmem + 2 * TSZ;
    float* Ps = fsmem + 3 * TSZ;

    const int bh = blockIdx.y;
    const int b  = bh / Hh;
    const int h  = bh % Hh;
    const int q0 = blockIdx.x * 64;
    const int tx = threadIdx.x & 15;
    const int ty = threadIdx.x >> 4;

    const float* qbase = g_qkv + (size_t)b * Nn * QKV_N + (size_t)h * Dd;
    const float* kbase = qbase + Cc;
    const float* vbase = qbase + 2 * Cc;

    // Load Q tile [64][Dd] via float4
    #pragma unroll
    for (int i = threadIdx.x; i < 64 * (Dd / 4); i += 256) {
        int r  = i >> 4;
        int c4 = (i & 15) << 2;
        float4 v = *(const float4*)&qbase[(size_t)(q0 + r) * QKV_N + c4];
        float* q = &Qs[r * TPAD + c4];
        q[0] = v.x; q[1] = v.y; q[2] = v.z; q[3] = v.w;
    }

    u64 op[4][2] = {};           // packed O accumulators: (o[i][0],o[i][1]), (o[i][2],o[i][3])
    float m[4], l[4];
    #pragma unroll
    for (int i = 0; i < 4; i++) { m[i] = -1e30f; l[i] = 0.0f; }

    const float scale = 0.125f;   // 1/sqrt(64)

    for (int k0 = 0; k0 < Nn; k0 += 64) {
        __syncthreads();   // previous iter's Ks/Vs/Ps reads done
        #pragma unroll
        for (int i = threadIdx.x; i < 64 * (Dd / 4); i += 256) {
            int r  = i >> 4;
            int c4 = (i & 15) << 2;
            float4 kv = *(const float4*)&kbase[(size_t)(k0 + r) * QKV_N + c4];
            float4 vv = *(const float4*)&vbase[(size_t)(k0 + r) * QKV_N + c4];
            float* kd = &Ks[r * TPAD + c4];
            float* vd = &Vs[r * TPAD + c4];
            kd[0] = kv.x; kd[1] = kv.y; kd[2] = kv.z; kd[3] = kv.w;
            vd[0] = vv.x; vd[1] = vv.y; vd[2] = vv.z; vd[3] = vv.w;
        }
        __syncthreads();   // also covers Qs on first iteration

        // S = Q K^T (packed pairs over j)
        u64 sp[4][2] = {};
        #pragma unroll 8
        for (int d = 0; d < Dd; d++) {
            float kv0 = Ks[(tx     ) * TPAD + d];
            float kv1 = Ks[(tx + 16) * TPAD + d];
            float kv2 = Ks[(tx + 32) * TPAD + d];
            float kv3 = Ks[(tx + 48) * TPAD + d];
            u64 kp0 = pk2(kv0, kv1);
            u64 kp1 = pk2(kv2, kv3);
            #pragma unroll
            for (int i = 0; i < 4; i++) {
                float a = Qs[(ty + 16 * i) * TPAD + d];
                u64 ad = pk2(a, a);
                fma2(sp[i][0], ad, kp0);
                fma2(sp[i][1], ad, kp1);
            }
        }

        // Unpack S, run scalar online softmax (identical math to baseline)
        #pragma unroll
        for (int i = 0; i < 4; i++) {
            float s[4];
            upk2(sp[i][0], s[0], s[1]);
            upk2(sp[i][1], s[2], s[3]);

            float tmax = -1e30f;
            #pragma unroll
            for (int j = 0; j < 4; j++) {
                s[j] *= scale;
                tmax = fmaxf(tmax, s[j]);
            }
            #pragma unroll
            for (int msk = 1; msk < 16; msk <<= 1)
                tmax = fmaxf(tmax, __shfl_xor_sync(0xffffffffu, tmax, msk));

            float newm = fmaxf(m[i], tmax);
            float psum = 0.0f;
            #pragma unroll
            for (int j = 0; j < 4; j++) {
                s[j] = __expf(s[j] - newm);
                psum += s[j];
            }
            #pragma unroll
            for (int msk = 1; msk < 16; msk <<= 1)
                psum += __shfl_xor_sync(0xffffffffu, psum, msk);

            float corr = __expf(m[i] - newm);
            l[i] = l[i] * corr + psum;
            m[i] = newm;
            u64 cp = pk2(corr, corr);
            op[i][0] = mul2(op[i][0], cp);
            op[i][1] = mul2(op[i][1], cp);

            // Stage P tile row group to smem for the PV product
            #pragma unroll
            for (int j = 0; j < 4; j++)
                Ps[(ty + 16 * i) * TPAD + tx + 16 * j] = s[j];
        }
        __syncthreads();

        // O += P @ V (packed pairs over k)
        #pragma unroll 8
        for (int j = 0; j < 64; j++) {
            float v0 = Vs[j * TPAD + tx     ];
            float v1 = Vs[j * TPAD + tx + 16];
            float v2 = Vs[j * TPAD + tx + 32];
            float v3 = Vs[j * TPAD + tx + 48];
            u64 vp0 = pk2(v0, v1);
            u64 vp1 = pk2(v2, v3);
            #pragma unroll
            for (int i = 0; i < 4; i++) {
                float p = Ps[(ty + 16 * i) * TPAD + j];
                u64 pd = pk2(p, p);
                fma2(op[i][0], pd, vp0);
                fma2(op[i][1], pd, vp1);
            }
        }
    }

    // Normalize and write y[b, q0+r, h*64 + d]
    #pragma unroll
    for (int i = 0; i < 4; i++) {
        float inv_l = 1.0f / l[i];
        int n = q0 + ty + 16 * i;
        float* yrow = g_y + (size_t)(b * Nn + n) * Cc + h * Dd;
        float o0, o1, o2, o3;
        upk2(op[i][0], o0, o1);
        upk2(op[i][1], o2, o3);
        yrow[tx     ] = o0 * inv_l;
        yrow[tx + 16] = o1 * inv_l;
        yrow[tx + 32] = o2 * inv_l;
        yrow[tx + 48] = o3 * inv_l;
    }
}

// ---------------------------------------------------------------------------
// Launch — binding identical to the PASSING round-10 version.
// ---------------------------------------------------------------------------
static inline bool size_is(int got, long long elems) {
    return got == (int)elems || got == (int)(elems * 4);
}

extern "C" void kernel_launch(void* const* d_in, const int* in_sizes, int n_in,
                              void* d_out, int out_size) {
    const float* x      = nullptr;
    const float* w_attn = nullptr;
    const float* w_proj = nullptr;

    if (n_in >= 3 &&
        size_is(in_sizes[0], (long long)M_TOT * Cc) &&
        size_is(in_sizes[1], (long long)Cc * QKV_N) &&
        size_is(in_sizes[2], (long long)Cc * Cc)) {
        x      = (const float*)d_in[0];
        w_attn = (const float*)d_in[1];
        w_proj = (const float*)d_in[2];
    } else {
        for (int i = 0; i < n_in; i++) {
            if      (size_is(in_sizes[i], (long long)M_TOT * Cc)) x      = (const float*)d_in[i];
            else if (size_is(in_sizes[i], (long long)Cc * QKV_N)) w_attn = (const float*)d_in[i];
            else if (size_is(in_sizes[i], (long long)Cc * Cc))    w_proj = (const float*)d_in[i];
        }
    }
    float* out = (float*)d_out;

    if (!x || !w_attn || !w_proj) {
        int n = M_TOT * Cc;
        sentinel_fill_kernel<<<(n + 255) / 256, 256>>>(out, n);
        return;
    }

    // 1) QKV projection: [8192,1024] @ [1024,3072]
    qkv_gemm_kernel<<<dim3(QKV_N / BN, M_TOT / BM), 256>>>(x, w_attn);

    // 2) Flash attention (fp32 SIMT, packed FFMA2 inner loops)
    {
        const int attn_smem = 4 * TSZ * (int)sizeof(float);   // 66,560 B
        cudaFuncSetAttribute(attn_kernel, cudaFuncAttributeMaxDynamicSharedMemorySize, attn_smem);
        attn_kernel<<<dim3(Nn / 64, Bb * Hh), 256, attn_smem>>>();
    }

    // 3) Output projection: [8192,1024] @ [1024,1024]
    proj_gemm_kernel<<<dim3(Cc / BN, M_TOT / BM), 256>>>(w_proj, out);
}